// round 7
// baseline (speedup 1.0000x reference)
#include <cuda_runtime.h>
#include <cuda_bf16.h>
#include <cuda_fp16.h>
#include <math.h>
#include <stdint.h>

// Problem constants
#define B_      128
#define S_      256
#define MW      21
#define VOCAB   100
#define ECHAR   50
#define EWORD   256
#define KW      5
#define T_OUT   17
#define NWORDS  (B_ * S_)       // 32768

// Scratch
__device__ float          g_P [VOCAB * KW * EWORD];
__device__ __nv_bfloat16  g_Yh[NWORDS * EWORD];
__device__ __nv_bfloat16  g_Yl[NWORDS * EWORD];
// Interleaved weights: row r = 2*n + pg (pg: 0=proj, 1=gate), [r][k]
__device__ __nv_bfloat16  g_Wh[512 * EWORD];
__device__ __nv_bfloat16  g_Wl[512 * EWORD];

typedef unsigned long long ull;

__device__ __forceinline__ uint32_t smem_u32(const void* p) {
    uint32_t a;
    asm("{ .reg .u64 t; cvta.to.shared.u64 t, %1; cvt.u32.u64 %0, t; }"
        : "=r"(a) : "l"(p));
    return a;
}

// ---- warp-level mma + cp.async (sm_80 baseline PTX) ----
#define LDSM4(r, addr) \
    asm volatile("ldmatrix.sync.aligned.m8n8.x4.shared.b16 {%0,%1,%2,%3}, [%4];" \
        : "=r"((r)[0]), "=r"((r)[1]), "=r"((r)[2]), "=r"((r)[3]) : "r"(addr))

#define MMA_BF16(d, a, b0, b1) \
    asm volatile("mma.sync.aligned.m16n8k16.row.col.f32.bf16.bf16.f32 " \
        "{%0,%1,%2,%3}, {%4,%5,%6,%7}, {%8,%9}, {%0,%1,%2,%3};" \
        : "+f"((d)[0]), "+f"((d)[1]), "+f"((d)[2]), "+f"((d)[3]) \
        : "r"((a)[0]), "r"((a)[1]), "r"((a)[2]), "r"((a)[3]), \
          "r"(b0), "r"(b1))

#define CP16(dst, src) \
    asm volatile("cp.async.cg.shared.global [%0], [%1], 16;" \
                 :: "r"(dst), "l"(src) : "memory")
#define CP_COMMIT() asm volatile("cp.async.commit_group;" ::: "memory")
#define CP_WAIT2()  asm volatile("cp.async.wait_group 2;" ::: "memory")
#define CP_WAIT1()  asm volatile("cp.async.wait_group 1;" ::: "memory")
#define CP_WAIT0()  asm volatile("cp.async.wait_group 0;" ::: "memory")

// ---------------------------------------------------------------------------
// Kernel 1: P[v,k,e] — block per e, staged in SMEM coalesced.
// ---------------------------------------------------------------------------
__global__ void __launch_bounds__(512)
precomputeP(const float* __restrict__ emb, const float* __restrict__ cw) {
    __shared__ float s_emb[VOCAB * ECHAR];
    __shared__ float s_cw[ECHAR * KW];
    const int e = blockIdx.x;
    const int tid = threadIdx.x;

    for (int i = tid; i < VOCAB * ECHAR; i += 512) s_emb[i] = emb[i];
    if (tid < ECHAR * KW) s_cw[tid] = cw[e * (ECHAR * KW) + tid];
    __syncthreads();

    if (tid < VOCAB * KW) {
        const int v = tid / KW;
        const int k = tid - v * KW;
        float a = 0.f;
#pragma unroll 10
        for (int c = 0; c < ECHAR; c++)
            a += s_cw[c * KW + k] * s_emb[v * ECHAR + c];
        g_P[v * (KW * EWORD) + k * EWORD + e] = a;
    }
}

// ---------------------------------------------------------------------------
// Kernel 2: conv-as-table-lookup + ReLU + maxpool, fp16 P table in SMEM.
// grid (128, 5): y<4 conv slices; y==4 W-split plane.
// ---------------------------------------------------------------------------
#define SY_STRIDE 257

__global__ void __launch_bounds__(512)
conv_max_kernel(const int* __restrict__ ps, const float* __restrict__ cb,
                const float* __restrict__ Wp, const float* __restrict__ Wg) {
    const int tid = threadIdx.x;

    if (blockIdx.y == 4) {
        const int idx = blockIdx.x * 512 + tid;
        const int n = idx >> 8, k = idx & 255;
        const float p = Wp[idx], g = Wg[idx];
        const __nv_bfloat16 ph = __float2bfloat16(p);
        const __nv_bfloat16 gh = __float2bfloat16(g);
        g_Wh[(2 * n + 0) * EWORD + k] = ph;
        g_Wl[(2 * n + 0) * EWORD + k] = __float2bfloat16(p - __bfloat162float(ph));
        g_Wh[(2 * n + 1) * EWORD + k] = gh;
        g_Wl[(2 * n + 1) * EWORD + k] = __float2bfloat16(g - __bfloat162float(gh));
        return;
    }

    extern __shared__ char smraw[];
    __half2* sPh = (__half2*)smraw;
    float*   sY  = (float*)(smraw + VOCAB * KW * 32 * 4);

    const int e0 = blockIdx.y * 64;
    const int w0 = blockIdx.x * 256;

    for (int i = tid; i < VOCAB * KW * 32; i += 512) {
        const int v  = i / 160;
        const int r  = i - v * 160;
        const int k  = r >> 5;
        const int ep = r & 31;
        const float2 f = *(const float2*)&g_P[v * (KW * EWORD) + k * EWORD
                                              + e0 + ep * 2];
        sPh[i] = __float22half2_rn(f);
    }
    __syncthreads();

    const int el2 = tid & 31;
    const int wl  = tid >> 5;
    const float2 bias = *(const float2*)&cb[e0 + el2 * 2];

    for (int it = 0; it < 16; it++) {
        const int wloc = it * 16 + wl;
        const int* cid = ps + (w0 + wloc) * MW;

        int off[MW];
#pragma unroll
        for (int j = 0; j < MW; j++)
            off[j] = __ldg(&cid[j]) * (KW * 32) + el2;

        float m0 = -1e30f, m1 = -1e30f;
#pragma unroll
        for (int t = 0; t < T_OUT; t++) {
            const __half2 u0 = sPh[off[t + 0] + 0 * 32];
            const __half2 u1 = sPh[off[t + 1] + 1 * 32];
            const __half2 u2 = sPh[off[t + 2] + 2 * 32];
            const __half2 u3 = sPh[off[t + 3] + 3 * 32];
            const __half2 u4 = sPh[off[t + 4] + 4 * 32];
            const __half2 s01 = __hadd2(u0, u1);
            const __half2 s23 = __hadd2(u2, u3);
            const float2 f01 = __half22float2(s01);
            const float2 f23 = __half22float2(s23);
            const float2 f4  = __half22float2(u4);
            m0 = fmaxf(m0, f01.x + f23.x + f4.x);
            m1 = fmaxf(m1, f01.y + f23.y + f4.y);
        }
        sY[(el2 * 2 + 0) * SY_STRIDE + wloc] = fmaxf(m0 + bias.x, 0.f);
        sY[(el2 * 2 + 1) * SY_STRIDE + wloc] = fmaxf(m1 + bias.y, 0.f);
    }
    __syncthreads();

    for (int i = tid; i < 64 * 256; i += 512) {
        const int w = i >> 6, e = i & 63;
        const float y = sY[e * SY_STRIDE + w];
        const int gi = (w0 + w) * EWORD + e0 + e;
        const __nv_bfloat16 yh = __float2bfloat16(y);
        g_Yh[gi] = yh;
        g_Yl[gi] = __float2bfloat16(y - __bfloat162float(yh));
    }
}

// ---------------------------------------------------------------------------
// Kernel 3: highway dual-GEMM, bf16 3-term split, 3-stage cp.async pipeline.
// CTA 512 thr (16 warps: wm4 x wn4), tile 128m x 128 interleaved rows.
// grid (256, 4). Per-warp 32m x 32rows: 8 LDSM / 24 MMA per ks, B hi/lo in
// separate registers (no WAR serialization).
// ---------------------------------------------------------------------------
#define RSTR    80
#define OFF_AH  0
#define OFF_AL  10240
#define OFF_BH  20480
#define OFF_BL  30720
#define STAGE_B 40960
#define SM3_B   (3 * STAGE_B)

static __device__ __forceinline__ void stage_chunk(uint32_t sb, int tid,
                                                   int m0, int rb, int kb) {
    const int r = tid >> 2, c = tid & 3;
    {
        const long gs = ((long)(m0 + r) * EWORD + kb + c * 8) * 2;
        CP16(sb + OFF_AH + r * RSTR + c * 16, (const char*)g_Yh + gs);
        CP16(sb + OFF_AL + r * RSTR + c * 16, (const char*)g_Yl + gs);
    }
    {
        const long gs = ((long)(rb + r) * EWORD + kb + c * 8) * 2;
        CP16(sb + OFF_BH + r * RSTR + c * 16, (const char*)g_Wh + gs);
        CP16(sb + OFF_BL + r * RSTR + c * 16, (const char*)g_Wl + gs);
    }
    CP_COMMIT();
}

__global__ void __launch_bounds__(512, 1)
highway_mma(const float* __restrict__ bp, const float* __restrict__ bg,
            float* __restrict__ out) {
    extern __shared__ char sm[];
    const uint32_t smb = smem_u32(sm);

    const int tid = threadIdx.x;
    const int wid = tid >> 5;
    const int lane = tid & 31;
    const int wm = wid & 3;          // 32m each
    const int wn = wid >> 2;         // 32 interleaved rows each
    const int m0 = blockIdx.x * 128;
    const int rb = blockIdx.y * 128;

    float acc[2][4][4];
#pragma unroll
    for (int i = 0; i < 2; i++)
#pragma unroll
        for (int j = 0; j < 4; j++)
#pragma unroll
            for (int c = 0; c < 4; c++) acc[i][j][c] = 0.f;

    const int laneRow = lane & 15;
    const int laneHi  = (lane >> 4) * 16;

    stage_chunk(smb + 0 * STAGE_B, tid, m0, rb, 0);
    stage_chunk(smb + 1 * STAGE_B, tid, m0, rb, 32);
    stage_chunk(smb + 2 * STAGE_B, tid, m0, rb, 64);

#pragma unroll
    for (int ch = 0; ch < 8; ch++) {
        if (ch <= 5) CP_WAIT2();
        else if (ch == 6) CP_WAIT1();
        else CP_WAIT0();
        __syncthreads();
        const uint32_t st = smb + (uint32_t)(ch % 3) * STAGE_B;

#pragma unroll
        for (int ks = 0; ks < 2; ks++) {
            const uint32_t kboff = ks * 32 + laneHi;

            uint32_t ah[2][4], al[2][4];
#pragma unroll
            for (int mt = 0; mt < 2; mt++) {
                const uint32_t ra = (wm * 32 + mt * 16 + laneRow) * RSTR + kboff;
                LDSM4(ah[mt], st + OFF_AH + ra);
                LDSM4(al[mt], st + OFF_AL + ra);
            }

            uint32_t bh0[4], bh1[4], bl0[4], bl1[4];
#pragma unroll
            for (int tp = 0; tp < 2; tp++) {
                const uint32_t rB = (wn * 32 + tp * 16 + laneRow) * RSTR + kboff;
                uint32_t q[4];
                LDSM4(q, st + OFF_BH + rB);
                bh0[2*tp] = q[0]; bh0[2*tp+1] = q[1];
                bh1[2*tp] = q[2]; bh1[2*tp+1] = q[3];
                uint32_t ql[4];
                LDSM4(ql, st + OFF_BL + rB);
                bl0[2*tp] = ql[0]; bl0[2*tp+1] = ql[1];
                bl1[2*tp] = ql[2]; bl1[2*tp+1] = ql[3];
            }

#pragma unroll
            for (int mt = 0; mt < 2; mt++)
#pragma unroll
                for (int j = 0; j < 4; j++) {
                    MMA_BF16(acc[mt][j], ah[mt], bh0[j], bh1[j]);
                    MMA_BF16(acc[mt][j], al[mt], bh0[j], bh1[j]);
                    MMA_BF16(acc[mt][j], ah[mt], bl0[j], bl1[j]);
                }
        }

        __syncthreads();
        if (ch + 3 < 8)
            stage_chunk(smb + (uint32_t)(ch % 3) * STAGE_B, tid, m0, rb,
                        (ch + 3) * 32);
    }

    // Fused highway epilogue; y reconstructed from the bf16 split.
    const int nq = blockIdx.y * 64 + wn * 16 + (lane & 3);
#pragma unroll
    for (int mt = 0; mt < 2; mt++) {
        const int mrow = m0 + wm * 32 + mt * 16 + (lane >> 2);
#pragma unroll
        for (int j = 0; j < 4; j++) {
            const int n = nq + j * 4;
            const float bpn = __ldg(&bp[n]);
            const float bgn = __ldg(&bg[n]);

            {
                const int gi = mrow * EWORD + n;
                const float y = __bfloat162float(g_Yh[gi])
                              + __bfloat162float(g_Yl[gi]);
                const float p = fmaxf(acc[mt][j][0] + bpn, 0.f);
                const float g = 1.f / (1.f + __expf(-(acc[mt][j][1] + bgn)));
                out[gi] = g * p + (1.f - g) * y;
            }
            {
                const int gi = (mrow + 8) * EWORD + n;
                const float y = __bfloat162float(g_Yh[gi])
                              + __bfloat162float(g_Yl[gi]);
                const float p = fmaxf(acc[mt][j][2] + bpn, 0.f);
                const float g = 1.f / (1.f + __expf(-(acc[mt][j][3] + bgn)));
                out[gi] = g * p + (1.f - g) * y;
            }
        }
    }
}

// ---------------------------------------------------------------------------
extern "C" void kernel_launch(void* const* d_in, const int* in_sizes, int n_in,
                              void* d_out, int out_size) {
    const int*   ps  = (const int*)d_in[0];
    const float* emb = (const float*)d_in[1];
    const float* cw  = (const float*)d_in[2];
    const float* cb  = (const float*)d_in[3];
    const float* wp  = (const float*)d_in[4];
    const float* bpv = (const float*)d_in[5];
    const float* wg  = (const float*)d_in[6];
    const float* bgv = (const float*)d_in[7];
    float* out = (float*)d_out;

    precomputeP<<<EWORD, 512>>>(emb, cw);

    const int smem2 = VOCAB * KW * 32 * 4 + 64 * SY_STRIDE * 4;
    cudaFuncSetAttribute(conv_max_kernel,
                         cudaFuncAttributeMaxDynamicSharedMemorySize, smem2);
    conv_max_kernel<<<dim3(128, 5), 512, smem2>>>(ps, cb, wp, wg);

    cudaFuncSetAttribute(highway_mma,
                         cudaFuncAttributeMaxDynamicSharedMemorySize, SM3_B);
    highway_mma<<<dim3(NWORDS / 128, 4), 512, SM3_B>>>(bpv, bgv, out);
}

// round 8
// speedup vs baseline: 1.2320x; 1.2320x over previous
#include <cuda_runtime.h>
#include <cuda_bf16.h>
#include <cuda_fp16.h>
#include <math.h>
#include <stdint.h>

// Problem constants
#define B_      128
#define S_      256
#define MW      21
#define VOCAB   100
#define ECHAR   50
#define EWORD   256
#define KW      5
#define T_OUT   17
#define NWORDS  (B_ * S_)       // 32768

// Scratch
__device__ float   g_P [VOCAB * KW * EWORD];
__device__ float   g_Y [NWORDS * EWORD];      // fp32 (exact passthrough)
__device__ __half  g_Yf[NWORDS * EWORD];      // fp16 Y (GEMM A operand)
// Interleaved weights: row r = 2*n + pg (pg: 0=proj, 1=gate), [r][k]
__device__ __half  g_Wh[512 * EWORD];         // fp16 hi
__device__ __half  g_Wl[512 * EWORD];         // fp16 residual

typedef unsigned long long ull;

__device__ __forceinline__ uint32_t smem_u32(const void* p) {
    uint32_t a;
    asm("{ .reg .u64 t; cvta.to.shared.u64 t, %1; cvt.u32.u64 %0, t; }"
        : "=r"(a) : "l"(p));
    return a;
}

// ---- warp-level mma + cp.async (sm_80 baseline PTX) ----
#define LDSM4(r, addr) \
    asm volatile("ldmatrix.sync.aligned.m8n8.x4.shared.b16 {%0,%1,%2,%3}, [%4];" \
        : "=r"((r)[0]), "=r"((r)[1]), "=r"((r)[2]), "=r"((r)[3]) : "r"(addr))

#define MMA_F16(d, a, b0, b1) \
    asm volatile("mma.sync.aligned.m16n8k16.row.col.f32.f16.f16.f32 " \
        "{%0,%1,%2,%3}, {%4,%5,%6,%7}, {%8,%9}, {%0,%1,%2,%3};" \
        : "+f"((d)[0]), "+f"((d)[1]), "+f"((d)[2]), "+f"((d)[3]) \
        : "r"((a)[0]), "r"((a)[1]), "r"((a)[2]), "r"((a)[3]), \
          "r"(b0), "r"(b1))

#define CP16(dst, src) \
    asm volatile("cp.async.cg.shared.global [%0], [%1], 16;" \
                 :: "r"(dst), "l"(src) : "memory")
#define CP_COMMIT() asm volatile("cp.async.commit_group;" ::: "memory")
#define CP_WAIT2()  asm volatile("cp.async.wait_group 2;" ::: "memory")
#define CP_WAIT1()  asm volatile("cp.async.wait_group 1;" ::: "memory")
#define CP_WAIT0()  asm volatile("cp.async.wait_group 0;" ::: "memory")

// ---------------------------------------------------------------------------
// Kernel 1: P[v,k,e] — block per e, staged in SMEM coalesced.
// ---------------------------------------------------------------------------
__global__ void __launch_bounds__(512)
precomputeP(const float* __restrict__ emb, const float* __restrict__ cw) {
    __shared__ float s_emb[VOCAB * ECHAR];
    __shared__ float s_cw[ECHAR * KW];
    const int e = blockIdx.x;
    const int tid = threadIdx.x;

    for (int i = tid; i < VOCAB * ECHAR; i += 512) s_emb[i] = emb[i];
    if (tid < ECHAR * KW) s_cw[tid] = cw[e * (ECHAR * KW) + tid];
    __syncthreads();

    if (tid < VOCAB * KW) {
        const int v = tid / KW;
        const int k = tid - v * KW;
        float a = 0.f;
#pragma unroll 10
        for (int c = 0; c < ECHAR; c++)
            a += s_cw[c * KW + k] * s_emb[v * ECHAR + c];
        g_P[v * (KW * EWORD) + k * EWORD + e] = a;
    }
}

// ---------------------------------------------------------------------------
// Kernel 2: conv-as-table-lookup + ReLU + maxpool, fp16 P table in SMEM.
// grid (128, 5): y<4 conv slices; y==4 W-split plane (fp16 hi/lo).
// ---------------------------------------------------------------------------
#define SY_STRIDE 257

__global__ void __launch_bounds__(512)
conv_max_kernel(const int* __restrict__ ps, const float* __restrict__ cb,
                const float* __restrict__ Wp, const float* __restrict__ Wg) {
    const int tid = threadIdx.x;

    if (blockIdx.y == 4) {
        const int idx = blockIdx.x * 512 + tid;
        const int n = idx >> 8, k = idx & 255;
        const float p = Wp[idx], g = Wg[idx];
        const __half ph = __float2half_rn(p);
        const __half gh = __float2half_rn(g);
        g_Wh[(2 * n + 0) * EWORD + k] = ph;
        g_Wl[(2 * n + 0) * EWORD + k] = __float2half_rn(p - __half2float(ph));
        g_Wh[(2 * n + 1) * EWORD + k] = gh;
        g_Wl[(2 * n + 1) * EWORD + k] = __float2half_rn(g - __half2float(gh));
        return;
    }

    extern __shared__ char smraw[];
    __half2* sPh = (__half2*)smraw;
    float*   sY  = (float*)(smraw + VOCAB * KW * 32 * 4);

    const int e0 = blockIdx.y * 64;
    const int w0 = blockIdx.x * 256;

    for (int i = tid; i < VOCAB * KW * 32; i += 512) {
        const int v  = i / 160;
        const int r  = i - v * 160;
        const int k  = r >> 5;
        const int ep = r & 31;
        const float2 f = *(const float2*)&g_P[v * (KW * EWORD) + k * EWORD
                                              + e0 + ep * 2];
        sPh[i] = __float22half2_rn(f);
    }
    __syncthreads();

    const int el2 = tid & 31;
    const int wl  = tid >> 5;
    const float2 bias = *(const float2*)&cb[e0 + el2 * 2];

    for (int it = 0; it < 16; it++) {
        const int wloc = it * 16 + wl;
        const int* cid = ps + (w0 + wloc) * MW;

        int off[MW];
#pragma unroll
        for (int j = 0; j < MW; j++)
            off[j] = __ldg(&cid[j]) * (KW * 32) + el2;

        float m0 = -1e30f, m1 = -1e30f;
#pragma unroll
        for (int t = 0; t < T_OUT; t++) {
            const __half2 u0 = sPh[off[t + 0] + 0 * 32];
            const __half2 u1 = sPh[off[t + 1] + 1 * 32];
            const __half2 u2 = sPh[off[t + 2] + 2 * 32];
            const __half2 u3 = sPh[off[t + 3] + 3 * 32];
            const __half2 u4 = sPh[off[t + 4] + 4 * 32];
            const __half2 s01 = __hadd2(u0, u1);
            const __half2 s23 = __hadd2(u2, u3);
            const float2 f01 = __half22float2(s01);
            const float2 f23 = __half22float2(s23);
            const float2 f4  = __half22float2(u4);
            m0 = fmaxf(m0, f01.x + f23.x + f4.x);
            m1 = fmaxf(m1, f01.y + f23.y + f4.y);
        }
        sY[(el2 * 2 + 0) * SY_STRIDE + wloc] = fmaxf(m0 + bias.x, 0.f);
        sY[(el2 * 2 + 1) * SY_STRIDE + wloc] = fmaxf(m1 + bias.y, 0.f);
    }
    __syncthreads();

    for (int i = tid; i < 64 * 256; i += 512) {
        const int w = i >> 6, e = i & 63;
        const float y = sY[e * SY_STRIDE + w];
        const int gi = (w0 + w) * EWORD + e0 + e;
        g_Y[gi]  = y;
        g_Yf[gi] = __float2half_rn(y);
    }
}

// ---------------------------------------------------------------------------
// Kernel 3: highway dual-GEMM, fp16 2-term split (A*Bh + A*Bl), 3-stage
// cp.async pipeline, 2 CTAs/SM. CTA 256 thr (8 warps: 2m x 4n), tile
// 128m x 128 interleaved rows. Warp tile 64m x 32 rows: 8 LDSM / 32 MMA
// per ks (B-fragment reuse 4x). grid (256, 4).
// ---------------------------------------------------------------------------
#define RSTR    80
#define OFF_A   0                       // 128 * 80 = 10240
#define OFF_BH  10240
#define OFF_BL  20480
#define STAGE_B 30720
#define SM3_B   (3 * STAGE_B)           // 92160

static __device__ __forceinline__ void stage_chunk(uint32_t sb, int tid,
                                                   int m0, int rb, int kb) {
#pragma unroll
    for (int q = 0; q < 2; q++) {
        const int idx = tid + q * 256;
        const int r = idx >> 2, c = idx & 3;
        const uint32_t so = r * RSTR + c * 16;
        CP16(sb + OFF_A + so,
             (const char*)g_Yf + ((long)(m0 + r) * EWORD + kb + c * 8) * 2);
        const long gw = ((long)(rb + r) * EWORD + kb + c * 8) * 2;
        CP16(sb + OFF_BH + so, (const char*)g_Wh + gw);
        CP16(sb + OFF_BL + so, (const char*)g_Wl + gw);
    }
    CP_COMMIT();
}

__global__ void __launch_bounds__(256, 2)
highway_mma(const float* __restrict__ bp, const float* __restrict__ bg,
            float* __restrict__ out) {
    extern __shared__ char sm[];
    const uint32_t smb = smem_u32(sm);

    const int tid = threadIdx.x;
    const int wid = tid >> 5;
    const int lane = tid & 31;
    const int wm = wid & 1;          // 64m each
    const int wn = wid >> 1;         // 32 interleaved rows each
    const int m0 = blockIdx.x * 128;
    const int rb = blockIdx.y * 128;

    float acc[4][4][4];
#pragma unroll
    for (int i = 0; i < 4; i++)
#pragma unroll
        for (int j = 0; j < 4; j++)
#pragma unroll
            for (int c = 0; c < 4; c++) acc[i][j][c] = 0.f;

    const int laneRow = lane & 15;
    const int laneHi  = (lane >> 4) * 16;

    stage_chunk(smb + 0 * STAGE_B, tid, m0, rb, 0);
    stage_chunk(smb + 1 * STAGE_B, tid, m0, rb, 32);
    stage_chunk(smb + 2 * STAGE_B, tid, m0, rb, 64);

#pragma unroll
    for (int ch = 0; ch < 8; ch++) {
        if (ch <= 5) CP_WAIT2();
        else if (ch == 6) CP_WAIT1();
        else CP_WAIT0();
        __syncthreads();
        const uint32_t st = smb + (uint32_t)(ch % 3) * STAGE_B;

#pragma unroll
        for (int ks = 0; ks < 2; ks++) {
            const uint32_t kboff = ks * 32 + laneHi;

            // A fragments: 4 m16 tiles (fp16, single term)
            uint32_t af[4][4];
#pragma unroll
            for (int mt = 0; mt < 4; mt++)
                LDSM4(af[mt], st + OFF_A
                      + (wm * 64 + mt * 16 + laneRow) * RSTR + kboff);

            // B fragments: 32 rows = 2 tiles, hi + lo in separate regs
            uint32_t bh0[4], bh1[4], bl0[4], bl1[4];
#pragma unroll
            for (int tp = 0; tp < 2; tp++) {
                const uint32_t rB = (wn * 32 + tp * 16 + laneRow) * RSTR + kboff;
                uint32_t q[4];
                LDSM4(q, st + OFF_BH + rB);
                bh0[2*tp] = q[0]; bh0[2*tp+1] = q[1];
                bh1[2*tp] = q[2]; bh1[2*tp+1] = q[3];
                uint32_t ql[4];
                LDSM4(ql, st + OFF_BL + rB);
                bl0[2*tp] = ql[0]; bl0[2*tp+1] = ql[1];
                bl1[2*tp] = ql[2]; bl1[2*tp+1] = ql[3];
            }

#pragma unroll
            for (int mt = 0; mt < 4; mt++)
#pragma unroll
                for (int j = 0; j < 4; j++) {
                    MMA_F16(acc[mt][j], af[mt], bh0[j], bh1[j]);
                    MMA_F16(acc[mt][j], af[mt], bl0[j], bl1[j]);
                }
        }

        __syncthreads();
        if (ch + 3 < 8)
            stage_chunk(smb + (uint32_t)(ch % 3) * STAGE_B, tid, m0, rb,
                        (ch + 3) * 32);
    }

    // Fused highway epilogue; exact fp32 y passthrough.
    const int nq = (rb >> 1) + wn * 16 + (lane & 3);
#pragma unroll
    for (int mt = 0; mt < 4; mt++) {
        const int mrow = m0 + wm * 64 + mt * 16 + (lane >> 2);
#pragma unroll
        for (int j = 0; j < 4; j++) {
            const int n = nq + j * 4;
            const float bpn = __ldg(&bp[n]);
            const float bgn = __ldg(&bg[n]);

            {
                const int gi = mrow * EWORD + n;
                const float y = g_Y[gi];
                const float p = fmaxf(acc[mt][j][0] + bpn, 0.f);
                const float g = 1.f / (1.f + __expf(-(acc[mt][j][1] + bgn)));
                out[gi] = g * p + (1.f - g) * y;
            }
            {
                const int gi = (mrow + 8) * EWORD + n;
                const float y = g_Y[gi];
                const float p = fmaxf(acc[mt][j][2] + bpn, 0.f);
                const float g = 1.f / (1.f + __expf(-(acc[mt][j][3] + bgn)));
                out[gi] = g * p + (1.f - g) * y;
            }
        }
    }
}

// ---------------------------------------------------------------------------
extern "C" void kernel_launch(void* const* d_in, const int* in_sizes, int n_in,
                              void* d_out, int out_size) {
    const int*   ps  = (const int*)d_in[0];
    const float* emb = (const float*)d_in[1];
    const float* cw  = (const float*)d_in[2];
    const float* cb  = (const float*)d_in[3];
    const float* wp  = (const float*)d_in[4];
    const float* bpv = (const float*)d_in[5];
    const float* wg  = (const float*)d_in[6];
    const float* bgv = (const float*)d_in[7];
    float* out = (float*)d_out;

    precomputeP<<<EWORD, 512>>>(emb, cw);

    const int smem2 = VOCAB * KW * 32 * 4 + 64 * SY_STRIDE * 4;
    cudaFuncSetAttribute(conv_max_kernel,
                         cudaFuncAttributeMaxDynamicSharedMemorySize, smem2);
    conv_max_kernel<<<dim3(128, 5), 512, smem2>>>(ps, cb, wp, wg);

    cudaFuncSetAttribute(highway_mma,
                         cudaFuncAttributeMaxDynamicSharedMemorySize, SM3_B);
    highway_mma<<<dim3(NWORDS / 128, 4), 256, SM3_B>>>(bpv, bgv, out);
}

// round 9
// speedup vs baseline: 1.2877x; 1.0452x over previous
#include <cuda_runtime.h>
#include <cuda_bf16.h>
#include <cuda_fp16.h>
#include <math.h>
#include <stdint.h>

// Problem constants
#define B_      128
#define S_      256
#define MW      21
#define VOCAB   100
#define ECHAR   50
#define EWORD   256
#define KW      5
#define T_OUT   17
#define NWORDS  (B_ * S_)       // 32768

// Scratch
__device__ float   g_P [VOCAB * KW * EWORD];
__device__ float   g_Y [NWORDS * EWORD];      // fp32 (exact passthrough)
__device__ __half  g_Yf[NWORDS * EWORD];      // fp16 Y (GEMM A operand)
// Interleaved weights: row r = 2*n + pg (pg: 0=proj, 1=gate), [r][k], fp16
__device__ __half  g_Wf[512 * EWORD];

typedef unsigned long long ull;

__device__ __forceinline__ uint32_t smem_u32(const void* p) {
    uint32_t a;
    asm("{ .reg .u64 t; cvta.to.shared.u64 t, %1; cvt.u32.u64 %0, t; }"
        : "=r"(a) : "l"(p));
    return a;
}

// ---- warp-level mma + cp.async (sm_80 baseline PTX) ----
#define LDSM4(r, addr) \
    asm volatile("ldmatrix.sync.aligned.m8n8.x4.shared.b16 {%0,%1,%2,%3}, [%4];" \
        : "=r"((r)[0]), "=r"((r)[1]), "=r"((r)[2]), "=r"((r)[3]) : "r"(addr))

#define MMA_F16(d, a, b0, b1) \
    asm volatile("mma.sync.aligned.m16n8k16.row.col.f32.f16.f16.f32 " \
        "{%0,%1,%2,%3}, {%4,%5,%6,%7}, {%8,%9}, {%0,%1,%2,%3};" \
        : "+f"((d)[0]), "+f"((d)[1]), "+f"((d)[2]), "+f"((d)[3]) \
        : "r"((a)[0]), "r"((a)[1]), "r"((a)[2]), "r"((a)[3]), \
          "r"(b0), "r"(b1))

#define CP16(dst, src) \
    asm volatile("cp.async.cg.shared.global [%0], [%1], 16;" \
                 :: "r"(dst), "l"(src) : "memory")
#define CP_COMMIT() asm volatile("cp.async.commit_group;" ::: "memory")
#define CP_WAIT3()  asm volatile("cp.async.wait_group 3;" ::: "memory")
#define CP_WAIT2()  asm volatile("cp.async.wait_group 2;" ::: "memory")
#define CP_WAIT1()  asm volatile("cp.async.wait_group 1;" ::: "memory")
#define CP_WAIT0()  asm volatile("cp.async.wait_group 0;" ::: "memory")

// ---------------------------------------------------------------------------
// Kernel 1: P[v,k,e] — 128 blocks x 2 e, staged in SMEM coalesced.
// ---------------------------------------------------------------------------
__global__ void __launch_bounds__(512)
precomputeP(const float* __restrict__ emb, const float* __restrict__ cw) {
    __shared__ float s_emb[VOCAB * ECHAR];      // 20 KB
    __shared__ float s_cw[2 * ECHAR * KW];      // 2 KB
    const int e0 = blockIdx.x * 2;
    const int tid = threadIdx.x;

    for (int i = tid; i < VOCAB * ECHAR; i += 512) s_emb[i] = emb[i];
    if (tid < 2 * ECHAR * KW)
        s_cw[tid] = cw[e0 * (ECHAR * KW) + tid];
    __syncthreads();

    for (int p = tid; p < VOCAB * KW * 2; p += 512) {
        const int v   = p / (KW * 2);
        const int rem = p - v * (KW * 2);
        const int k   = rem >> 1;
        const int ei  = rem & 1;
        float a = 0.f;
#pragma unroll 10
        for (int c = 0; c < ECHAR; c++)
            a += s_cw[ei * (ECHAR * KW) + c * KW + k] * s_emb[v * ECHAR + c];
        g_P[v * (KW * EWORD) + k * EWORD + e0 + ei] = a;
    }
}

// ---------------------------------------------------------------------------
// Kernel 2: conv-as-table-lookup + ReLU + maxpool, fp16 P table in SMEM.
// grid (128, 5): y<4 conv slices; y==4 W fp16 convert plane.
// ---------------------------------------------------------------------------
#define SY_STRIDE 257

__global__ void __launch_bounds__(512)
conv_max_kernel(const int* __restrict__ ps, const float* __restrict__ cb,
                const float* __restrict__ Wp, const float* __restrict__ Wg) {
    const int tid = threadIdx.x;

    if (blockIdx.y == 4) {
        const int idx = blockIdx.x * 512 + tid;
        const int n = idx >> 8, k = idx & 255;
        g_Wf[(2 * n + 0) * EWORD + k] = __float2half_rn(Wp[idx]);
        g_Wf[(2 * n + 1) * EWORD + k] = __float2half_rn(Wg[idx]);
        return;
    }

    extern __shared__ char smraw[];
    __half2* sPh = (__half2*)smraw;
    float*   sY  = (float*)(smraw + VOCAB * KW * 32 * 4);

    const int e0 = blockIdx.y * 64;
    const int w0 = blockIdx.x * 256;

    for (int i = tid; i < VOCAB * KW * 32; i += 512) {
        const int v  = i / 160;
        const int r  = i - v * 160;
        const int k  = r >> 5;
        const int ep = r & 31;
        const float2 f = *(const float2*)&g_P[v * (KW * EWORD) + k * EWORD
                                              + e0 + ep * 2];
        sPh[i] = __float22half2_rn(f);
    }
    __syncthreads();

    const int el2 = tid & 31;
    const int wl  = tid >> 5;
    const float2 bias = *(const float2*)&cb[e0 + el2 * 2];

    for (int it = 0; it < 16; it++) {
        const int wloc = it * 16 + wl;
        const int* cid = ps + (w0 + wloc) * MW;

        int off[MW];
#pragma unroll
        for (int j = 0; j < MW; j++)
            off[j] = __ldg(&cid[j]) * (KW * 32) + el2;

        float m0 = -1e30f, m1 = -1e30f;
#pragma unroll
        for (int t = 0; t < T_OUT; t++) {
            const __half2 u0 = sPh[off[t + 0] + 0 * 32];
            const __half2 u1 = sPh[off[t + 1] + 1 * 32];
            const __half2 u2 = sPh[off[t + 2] + 2 * 32];
            const __half2 u3 = sPh[off[t + 3] + 3 * 32];
            const __half2 u4 = sPh[off[t + 4] + 4 * 32];
            const __half2 s01 = __hadd2(u0, u1);
            const __half2 s23 = __hadd2(u2, u3);
            const float2 f01 = __half22float2(s01);
            const float2 f23 = __half22float2(s23);
            const float2 f4  = __half22float2(u4);
            m0 = fmaxf(m0, f01.x + f23.x + f4.x);
            m1 = fmaxf(m1, f01.y + f23.y + f4.y);
        }
        sY[(el2 * 2 + 0) * SY_STRIDE + wloc] = fmaxf(m0 + bias.x, 0.f);
        sY[(el2 * 2 + 1) * SY_STRIDE + wloc] = fmaxf(m1 + bias.y, 0.f);
    }
    __syncthreads();

    for (int i = tid; i < 64 * 256; i += 512) {
        const int w = i >> 6, e = i & 63;
        const float y = sY[e * SY_STRIDE + w];
        const int gi = (w0 + w) * EWORD + e0 + e;
        g_Y[gi]  = y;
        g_Yf[gi] = __float2half_rn(y);
    }
}

// ---------------------------------------------------------------------------
// Kernel 3: highway dual-GEMM, single-term fp16 (A*B), 4-stage cp.async
// pipeline, 2 CTAs/SM. CTA 256 thr (8 warps: 2m x 4n), tile 128m x 128
// interleaved rows. Warp tile 64m x 32 rows: 6 LDSM / 16 MMA per ks.
// grid (256, 4).
// ---------------------------------------------------------------------------
#define RSTR    80
#define OFF_A   0                       // 128 * 80 = 10240
#define OFF_B   10240
#define STAGE_B 20480
#define SM3_B   (4 * STAGE_B)           // 81920

static __device__ __forceinline__ void stage_chunk(uint32_t sb, int tid,
                                                   int m0, int rb, int kb) {
#pragma unroll
    for (int q = 0; q < 2; q++) {
        const int idx = tid + q * 256;
        const int r = idx >> 2, c = idx & 3;
        const uint32_t so = r * RSTR + c * 16;
        CP16(sb + OFF_A + so,
             (const char*)g_Yf + ((long)(m0 + r) * EWORD + kb + c * 8) * 2);
        CP16(sb + OFF_B + so,
             (const char*)g_Wf + ((long)(rb + r) * EWORD + kb + c * 8) * 2);
    }
    CP_COMMIT();
}

__global__ void __launch_bounds__(256, 2)
highway_mma(const float* __restrict__ bp, const float* __restrict__ bg,
            float* __restrict__ out) {
    extern __shared__ char sm[];
    const uint32_t smb = smem_u32(sm);

    const int tid = threadIdx.x;
    const int wid = tid >> 5;
    const int lane = tid & 31;
    const int wm = wid & 1;          // 64m each
    const int wn = wid >> 1;         // 32 interleaved rows each
    const int m0 = blockIdx.x * 128;
    const int rb = blockIdx.y * 128;

    float acc[4][4][4];
#pragma unroll
    for (int i = 0; i < 4; i++)
#pragma unroll
        for (int j = 0; j < 4; j++)
#pragma unroll
            for (int c = 0; c < 4; c++) acc[i][j][c] = 0.f;

    const int laneRow = lane & 15;
    const int laneHi  = (lane >> 4) * 16;

    stage_chunk(smb + 0 * STAGE_B, tid, m0, rb, 0);
    stage_chunk(smb + 1 * STAGE_B, tid, m0, rb, 32);
    stage_chunk(smb + 2 * STAGE_B, tid, m0, rb, 64);
    stage_chunk(smb + 3 * STAGE_B, tid, m0, rb, 96);

#pragma unroll
    for (int ch = 0; ch < 8; ch++) {
        if (ch <= 4) CP_WAIT3();
        else if (ch == 5) CP_WAIT2();
        else if (ch == 6) CP_WAIT1();
        else CP_WAIT0();
        __syncthreads();
        const uint32_t st = smb + (uint32_t)(ch & 3) * STAGE_B;

#pragma unroll
        for (int ks = 0; ks < 2; ks++) {
            const uint32_t kboff = ks * 32 + laneHi;

            // A fragments: 4 m16 tiles
            uint32_t af[4][4];
#pragma unroll
            for (int mt = 0; mt < 4; mt++)
                LDSM4(af[mt], st + OFF_A
                      + (wm * 64 + mt * 16 + laneRow) * RSTR + kboff);

            // B fragments: 32 rows = 2 x4-tiles
            uint32_t b0[4], b1[4];
#pragma unroll
            for (int tp = 0; tp < 2; tp++) {
                uint32_t q[4];
                LDSM4(q, st + OFF_B
                      + (wn * 32 + tp * 16 + laneRow) * RSTR + kboff);
                b0[2*tp] = q[0]; b0[2*tp+1] = q[1];
                b1[2*tp] = q[2]; b1[2*tp+1] = q[3];
            }

#pragma unroll
            for (int mt = 0; mt < 4; mt++)
#pragma unroll
                for (int j = 0; j < 4; j++)
                    MMA_F16(acc[mt][j], af[mt], b0[j], b1[j]);
        }

        __syncthreads();
        if (ch + 4 < 8)
            stage_chunk(smb + (uint32_t)(ch & 3) * STAGE_B, tid, m0, rb,
                        (ch + 4) * 32);
    }

    // Fused highway epilogue; exact fp32 y passthrough.
    const int nq = (rb >> 1) + wn * 16 + (lane & 3);
#pragma unroll
    for (int mt = 0; mt < 4; mt++) {
        const int mrow = m0 + wm * 64 + mt * 16 + (lane >> 2);
#pragma unroll
        for (int j = 0; j < 4; j++) {
            const int n = nq + j * 4;
            const float bpn = __ldg(&bp[n]);
            const float bgn = __ldg(&bg[n]);

            {
                const int gi = mrow * EWORD + n;
                const float y = g_Y[gi];
                const float p = fmaxf(acc[mt][j][0] + bpn, 0.f);
                const float g = 1.f / (1.f + __expf(-(acc[mt][j][1] + bgn)));
                out[gi] = g * p + (1.f - g) * y;
            }
            {
                const int gi = (mrow + 8) * EWORD + n;
                const float y = g_Y[gi];
                const float p = fmaxf(acc[mt][j][2] + bpn, 0.f);
                const float g = 1.f / (1.f + __expf(-(acc[mt][j][3] + bgn)));
                out[gi] = g * p + (1.f - g) * y;
            }
        }
    }
}

// ---------------------------------------------------------------------------
extern "C" void kernel_launch(void* const* d_in, const int* in_sizes, int n_in,
                              void* d_out, int out_size) {
    const int*   ps  = (const int*)d_in[0];
    const float* emb = (const float*)d_in[1];
    const float* cw  = (const float*)d_in[2];
    const float* cb  = (const float*)d_in[3];
    const float* wp  = (const float*)d_in[4];
    const float* bpv = (const float*)d_in[5];
    const float* wg  = (const float*)d_in[6];
    const float* bgv = (const float*)d_in[7];
    float* out = (float*)d_out;

    precomputeP<<<EWORD / 2, 512>>>(emb, cw);

    const int smem2 = VOCAB * KW * 32 * 4 + 64 * SY_STRIDE * 4;
    cudaFuncSetAttribute(conv_max_kernel,
                         cudaFuncAttributeMaxDynamicSharedMemorySize, smem2);
    conv_max_kernel<<<dim3(128, 5), 512, smem2>>>(ps, cb, wp, wg);

    cudaFuncSetAttribute(highway_mma,
                         cudaFuncAttributeMaxDynamicSharedMemorySize, SM3_B);
    highway_mma<<<dim3(NWORDS / 128, 4), 256, SM3_B>>>(bpv, bgv, out);
}

// round 10
// speedup vs baseline: 1.3812x; 1.0726x over previous
#include <cuda_runtime.h>
#include <cuda_bf16.h>
#include <cuda_fp16.h>
#include <math.h>
#include <stdint.h>

// Problem constants
#define B_      128
#define S_      256
#define MW      21
#define VOCAB   100
#define ECHAR   50
#define EWORD   256
#define KW      5
#define T_OUT   17
#define NWORDS  (B_ * S_)       // 32768

// Scratch
__device__ float   g_P [VOCAB * KW * EWORD];
__device__ float   g_Y [NWORDS * EWORD];      // fp32 (exact passthrough)
__device__ __half  g_Yf[NWORDS * EWORD];      // fp16 Y (GEMM A operand)
// Interleaved weights: row r = 2*n + pg (pg: 0=proj, 1=gate), [r][k], fp16
__device__ __half  g_Wf[512 * EWORD];

typedef unsigned long long ull;

__device__ __forceinline__ uint32_t smem_u32(const void* p) {
    uint32_t a;
    asm("{ .reg .u64 t; cvta.to.shared.u64 t, %1; cvt.u32.u64 %0, t; }"
        : "=r"(a) : "l"(p));
    return a;
}

// ---- warp-level mma + cp.async (sm_80 baseline PTX) ----
#define LDSM4(r, addr) \
    asm volatile("ldmatrix.sync.aligned.m8n8.x4.shared.b16 {%0,%1,%2,%3}, [%4];" \
        : "=r"((r)[0]), "=r"((r)[1]), "=r"((r)[2]), "=r"((r)[3]) : "r"(addr))

#define MMA_F16(d, a, b0, b1) \
    asm volatile("mma.sync.aligned.m16n8k16.row.col.f32.f16.f16.f32 " \
        "{%0,%1,%2,%3}, {%4,%5,%6,%7}, {%8,%9}, {%0,%1,%2,%3};" \
        : "+f"((d)[0]), "+f"((d)[1]), "+f"((d)[2]), "+f"((d)[3]) \
        : "r"((a)[0]), "r"((a)[1]), "r"((a)[2]), "r"((a)[3]), \
          "r"(b0), "r"(b1))

#define CP16(dst, src) \
    asm volatile("cp.async.cg.shared.global [%0], [%1], 16;" \
                 :: "r"(dst), "l"(src) : "memory")
#define CP_COMMIT() asm volatile("cp.async.commit_group;" ::: "memory")
#define CP_WAIT2()  asm volatile("cp.async.wait_group 2;" ::: "memory")
#define CP_WAIT1()  asm volatile("cp.async.wait_group 1;" ::: "memory")
#define CP_WAIT0()  asm volatile("cp.async.wait_group 0;" ::: "memory")

// ---------------------------------------------------------------------------
// Kernel 1: P[v,k,e] — 128 blocks x 2 e, staged in SMEM coalesced.
// ---------------------------------------------------------------------------
__global__ void __launch_bounds__(512)
precomputeP(const float* __restrict__ emb, const float* __restrict__ cw) {
    __shared__ float s_emb[VOCAB * ECHAR];
    __shared__ float s_cw[2 * ECHAR * KW];
    const int e0 = blockIdx.x * 2;
    const int tid = threadIdx.x;

    for (int i = tid; i < VOCAB * ECHAR; i += 512) s_emb[i] = emb[i];
    if (tid < 2 * ECHAR * KW)
        s_cw[tid] = cw[e0 * (ECHAR * KW) + tid];
    __syncthreads();

    for (int p = tid; p < VOCAB * KW * 2; p += 512) {
        const int v   = p / (KW * 2);
        const int rem = p - v * (KW * 2);
        const int k   = rem >> 1;
        const int ei  = rem & 1;
        float a = 0.f;
#pragma unroll 10
        for (int c = 0; c < ECHAR; c++)
            a += s_cw[ei * (ECHAR * KW) + c * KW + k] * s_emb[v * ECHAR + c];
        g_P[v * (KW * EWORD) + k * EWORD + e0 + ei] = a;
    }
}

// ---------------------------------------------------------------------------
// Kernel 2: conv-as-table-lookup + ReLU + maxpool — fully fp16 inner loop.
// grid (128, 5): y<4 conv slices; y==4 W fp16 convert plane.
// ---------------------------------------------------------------------------
#define SY_STRIDE 257

__global__ void __launch_bounds__(512)
conv_max_kernel(const int* __restrict__ ps, const float* __restrict__ cb,
                const float* __restrict__ Wp, const float* __restrict__ Wg) {
    const int tid = threadIdx.x;

    if (blockIdx.y == 4) {
        const int idx = blockIdx.x * 512 + tid;
        const int n = idx >> 8, k = idx & 255;
        g_Wf[(2 * n + 0) * EWORD + k] = __float2half_rn(Wp[idx]);
        g_Wf[(2 * n + 1) * EWORD + k] = __float2half_rn(Wg[idx]);
        return;
    }

    extern __shared__ char smraw[];
    __half2* sPh = (__half2*)smraw;
    float*   sY  = (float*)(smraw + VOCAB * KW * 32 * 4);

    const int e0 = blockIdx.y * 64;
    const int w0 = blockIdx.x * 256;

    for (int i = tid; i < VOCAB * KW * 32; i += 512) {
        const int v  = i / 160;
        const int r  = i - v * 160;
        const int k  = r >> 5;
        const int ep = r & 31;
        const float2 f = *(const float2*)&g_P[v * (KW * EWORD) + k * EWORD
                                              + e0 + ep * 2];
        sPh[i] = __float22half2_rn(f);
    }
    __syncthreads();

    const int el2 = tid & 31;
    const int wl  = tid >> 5;
    const float2 bias = *(const float2*)&cb[e0 + el2 * 2];

    for (int it = 0; it < 16; it++) {
        const int wloc = it * 16 + wl;
        const int* cid = ps + (w0 + wloc) * MW;

        int off[MW];
#pragma unroll
        for (int j = 0; j < MW; j++)
            off[j] = __ldg(&cid[j]) * (KW * 32) + el2;

        __half2 mh = __float2half2_rn(-60000.f);
#pragma unroll
        for (int t = 0; t < T_OUT; t++) {
            const __half2 u0 = sPh[off[t + 0] + 0 * 32];
            const __half2 u1 = sPh[off[t + 1] + 1 * 32];
            const __half2 u2 = sPh[off[t + 2] + 2 * 32];
            const __half2 u3 = sPh[off[t + 3] + 3 * 32];
            const __half2 u4 = sPh[off[t + 4] + 4 * 32];
            const __half2 s = __hadd2(__hadd2(__hadd2(u0, u1),
                                              __hadd2(u2, u3)), u4);
            mh = __hmax2(mh, s);
        }
        const float2 f = __half22float2(mh);
        sY[(el2 * 2 + 0) * SY_STRIDE + wloc] = fmaxf(f.x + bias.x, 0.f);
        sY[(el2 * 2 + 1) * SY_STRIDE + wloc] = fmaxf(f.y + bias.y, 0.f);
    }
    __syncthreads();

    for (int i = tid; i < 64 * 256; i += 512) {
        const int w = i >> 6, e = i & 63;
        const float y = sY[e * SY_STRIDE + w];
        const int gi = (w0 + w) * EWORD + e0 + e;
        g_Y[gi]  = y;
        g_Yf[gi] = __float2half_rn(y);
    }
}

// ---------------------------------------------------------------------------
// Kernel 3: highway dual-GEMM, single-term fp16, K-chunks of 64, 4 chunks,
// 3-stage cp.async pipeline, 2 CTAs/SM. CTA 256 thr (8 warps: 2m x 4n),
// tile 128m x 128 interleaved rows. grid (256, 4).
// ---------------------------------------------------------------------------
#define RSTR    144                     // 128B data + 16B pad (9*16 odd)
#define OFF_A   0                       // 128 * 144 = 18432
#define OFF_B   18432
#define STAGE_B 36864
#define SM3_B   (3 * STAGE_B)           // 110592

static __device__ __forceinline__ void stage_chunk(uint32_t sb, int tid,
                                                   int m0, int rb, int kb) {
#pragma unroll
    for (int q = 0; q < 4; q++) {
        const int idx = tid + q * 256;
        const int r = idx >> 3, c = idx & 7;
        const uint32_t so = r * RSTR + c * 16;
        CP16(sb + OFF_A + so,
             (const char*)g_Yf + ((long)(m0 + r) * EWORD + kb + c * 8) * 2);
        CP16(sb + OFF_B + so,
             (const char*)g_Wf + ((long)(rb + r) * EWORD + kb + c * 8) * 2);
    }
    CP_COMMIT();
}

__global__ void __launch_bounds__(256, 2)
highway_mma(const float* __restrict__ bp, const float* __restrict__ bg,
            float* __restrict__ out) {
    extern __shared__ char sm[];
    const uint32_t smb = smem_u32(sm);

    const int tid = threadIdx.x;
    const int wid = tid >> 5;
    const int lane = tid & 31;
    const int wm = wid & 1;          // 64m each
    const int wn = wid >> 1;         // 32 interleaved rows each
    const int m0 = blockIdx.x * 128;
    const int rb = blockIdx.y * 128;

    float acc[4][4][4];
#pragma unroll
    for (int i = 0; i < 4; i++)
#pragma unroll
        for (int j = 0; j < 4; j++)
#pragma unroll
            for (int c = 0; c < 4; c++) acc[i][j][c] = 0.f;

    const int laneRow = lane & 15;
    const int laneHi  = (lane >> 4) * 16;

    stage_chunk(smb + 0 * STAGE_B, tid, m0, rb, 0);
    stage_chunk(smb + 1 * STAGE_B, tid, m0, rb, 64);
    stage_chunk(smb + 2 * STAGE_B, tid, m0, rb, 128);

#pragma unroll
    for (int ch = 0; ch < 4; ch++) {
        if (ch <= 1) CP_WAIT2();
        else if (ch == 2) CP_WAIT1();
        else CP_WAIT0();
        __syncthreads();
        const uint32_t st = smb + (uint32_t)(ch % 3) * STAGE_B;

#pragma unroll
        for (int ks = 0; ks < 4; ks++) {
            const uint32_t kboff = ks * 32 + laneHi;

            uint32_t af[4][4];
#pragma unroll
            for (int mt = 0; mt < 4; mt++)
                LDSM4(af[mt], st + OFF_A
                      + (wm * 64 + mt * 16 + laneRow) * RSTR + kboff);

            uint32_t b0[4], b1[4];
#pragma unroll
            for (int tp = 0; tp < 2; tp++) {
                uint32_t q[4];
                LDSM4(q, st + OFF_B
                      + (wn * 32 + tp * 16 + laneRow) * RSTR + kboff);
                b0[2*tp] = q[0]; b0[2*tp+1] = q[1];
                b1[2*tp] = q[2]; b1[2*tp+1] = q[3];
            }

#pragma unroll
            for (int mt = 0; mt < 4; mt++)
#pragma unroll
                for (int j = 0; j < 4; j++)
                    MMA_F16(acc[mt][j], af[mt], b0[j], b1[j]);
        }

        __syncthreads();
        if (ch + 3 < 4)
            stage_chunk(smb + (uint32_t)(ch % 3) * STAGE_B, tid, m0, rb,
                        (ch + 3) * 64);
    }

    // Fused highway epilogue; exact fp32 y passthrough.
    const int nq = (rb >> 1) + wn * 16 + (lane & 3);
#pragma unroll
    for (int mt = 0; mt < 4; mt++) {
        const int mrow = m0 + wm * 64 + mt * 16 + (lane >> 2);
#pragma unroll
        for (int j = 0; j < 4; j++) {
            const int n = nq + j * 4;
            const float bpn = __ldg(&bp[n]);
            const float bgn = __ldg(&bg[n]);

            {
                const int gi = mrow * EWORD + n;
                const float y = g_Y[gi];
                const float p = fmaxf(acc[mt][j][0] + bpn, 0.f);
                const float g = 1.f / (1.f + __expf(-(acc[mt][j][1] + bgn)));
                out[gi] = g * p + (1.f - g) * y;
            }
            {
                const int gi = (mrow + 8) * EWORD + n;
                const float y = g_Y[gi];
                const float p = fmaxf(acc[mt][j][2] + bpn, 0.f);
                const float g = 1.f / (1.f + __expf(-(acc[mt][j][3] + bgn)));
                out[gi] = g * p + (1.f - g) * y;
            }
        }
    }
}

// ---------------------------------------------------------------------------
extern "C" void kernel_launch(void* const* d_in, const int* in_sizes, int n_in,
                              void* d_out, int out_size) {
    const int*   ps  = (const int*)d_in[0];
    const float* emb = (const float*)d_in[1];
    const float* cw  = (const float*)d_in[2];
    const float* cb  = (const float*)d_in[3];
    const float* wp  = (const float*)d_in[4];
    const float* bpv = (const float*)d_in[5];
    const float* wg  = (const float*)d_in[6];
    const float* bgv = (const float*)d_in[7];
    float* out = (float*)d_out;

    precomputeP<<<EWORD / 2, 512>>>(emb, cw);

    const int smem2 = VOCAB * KW * 32 * 4 + 64 * SY_STRIDE * 4;
    cudaFuncSetAttribute(conv_max_kernel,
                         cudaFuncAttributeMaxDynamicSharedMemorySize, smem2);
    conv_max_kernel<<<dim3(128, 5), 512, smem2>>>(ps, cb, wp, wg);

    cudaFuncSetAttribute(highway_mma,
                         cudaFuncAttributeMaxDynamicSharedMemorySize, SM3_B);
    highway_mma<<<dim3(NWORDS / 128, 4), 256, SM3_B>>>(bpv, bgv, out);
}

// round 11
// speedup vs baseline: 1.4464x; 1.0472x over previous
#include <cuda_runtime.h>
#include <cuda_bf16.h>
#include <cuda_fp16.h>
#include <math.h>
#include <stdint.h>

// Problem constants
#define B_      128
#define S_      256
#define MW      21
#define VOCAB   100
#define ECHAR   50
#define EWORD   256
#define KW      5
#define T_OUT   17
#define NWORDS  (B_ * S_)       // 32768

// Scratch
__device__ float   g_P [VOCAB * KW * EWORD];
__device__ float   g_Y [NWORDS * EWORD];      // fp32 (exact passthrough)
__device__ __half  g_Yf[NWORDS * EWORD];      // fp16 Y (GEMM A operand)
// Interleaved weights: row r = 2*n + pg (pg: 0=proj, 1=gate), [r][k], fp16
__device__ __half  g_Wf[512 * EWORD];

typedef unsigned long long ull;

__device__ __forceinline__ uint32_t smem_u32(const void* p) {
    uint32_t a;
    asm("{ .reg .u64 t; cvta.to.shared.u64 t, %1; cvt.u32.u64 %0, t; }"
        : "=r"(a) : "l"(p));
    return a;
}

// ---- warp-level mma + cp.async (sm_80 baseline PTX) ----
#define LDSM4(r, addr) \
    asm volatile("ldmatrix.sync.aligned.m8n8.x4.shared.b16 {%0,%1,%2,%3}, [%4];" \
        : "=r"((r)[0]), "=r"((r)[1]), "=r"((r)[2]), "=r"((r)[3]) : "r"(addr))

#define MMA_F16(d, a, b0, b1) \
    asm volatile("mma.sync.aligned.m16n8k16.row.col.f32.f16.f16.f32 " \
        "{%0,%1,%2,%3}, {%4,%5,%6,%7}, {%8,%9}, {%0,%1,%2,%3};" \
        : "+f"((d)[0]), "+f"((d)[1]), "+f"((d)[2]), "+f"((d)[3]) \
        : "r"((a)[0]), "r"((a)[1]), "r"((a)[2]), "r"((a)[3]), \
          "r"(b0), "r"(b1))

#define CP16(dst, src) \
    asm volatile("cp.async.cg.shared.global [%0], [%1], 16;" \
                 :: "r"(dst), "l"(src) : "memory")
#define CP_COMMIT() asm volatile("cp.async.commit_group;" ::: "memory")
#define CP_WAIT2()  asm volatile("cp.async.wait_group 2;" ::: "memory")
#define CP_WAIT1()  asm volatile("cp.async.wait_group 1;" ::: "memory")
#define CP_WAIT0()  asm volatile("cp.async.wait_group 0;" ::: "memory")

// ---------------------------------------------------------------------------
// Kernel 1: P[v,k,e] — 128 blocks x 2 e, staged in SMEM coalesced.
// ---------------------------------------------------------------------------
__global__ void __launch_bounds__(512)
precomputeP(const float* __restrict__ emb, const float* __restrict__ cw) {
    __shared__ float s_emb[VOCAB * ECHAR];
    __shared__ float s_cw[2 * ECHAR * KW];
    const int e0 = blockIdx.x * 2;
    const int tid = threadIdx.x;

    for (int i = tid; i < VOCAB * ECHAR; i += 512) s_emb[i] = emb[i];
    if (tid < 2 * ECHAR * KW)
        s_cw[tid] = cw[e0 * (ECHAR * KW) + tid];
    __syncthreads();

    for (int p = tid; p < VOCAB * KW * 2; p += 512) {
        const int v   = p / (KW * 2);
        const int rem = p - v * (KW * 2);
        const int k   = rem >> 1;
        const int ei  = rem & 1;
        float a = 0.f;
#pragma unroll 10
        for (int c = 0; c < ECHAR; c++)
            a += s_cw[ei * (ECHAR * KW) + c * KW + k] * s_emb[v * ECHAR + c];
        g_P[v * (KW * EWORD) + k * EWORD + e0 + ei] = a;
    }
}

// ---------------------------------------------------------------------------
// Kernel 2: conv-as-table-lookup + ReLU + maxpool — fully fp16 inner loop.
// grid (128, 5): y<4 conv slices; y==4 W fp16 convert plane.
// ---------------------------------------------------------------------------
#define SY_STRIDE 257

__global__ void __launch_bounds__(512)
conv_max_kernel(const int* __restrict__ ps, const float* __restrict__ cb,
                const float* __restrict__ Wp, const float* __restrict__ Wg) {
    const int tid = threadIdx.x;

    if (blockIdx.y == 4) {
        const int idx = blockIdx.x * 512 + tid;
        const int n = idx >> 8, k = idx & 255;
        g_Wf[(2 * n + 0) * EWORD + k] = __float2half_rn(Wp[idx]);
        g_Wf[(2 * n + 1) * EWORD + k] = __float2half_rn(Wg[idx]);
        return;
    }

    extern __shared__ char smraw[];
    __half2* sPh = (__half2*)smraw;
    float*   sY  = (float*)(smraw + VOCAB * KW * 32 * 4);

    const int e0 = blockIdx.y * 64;
    const int w0 = blockIdx.x * 256;

    for (int i = tid; i < VOCAB * KW * 32; i += 512) {
        const int v  = i / 160;
        const int r  = i - v * 160;
        const int k  = r >> 5;
        const int ep = r & 31;
        const float2 f = *(const float2*)&g_P[v * (KW * EWORD) + k * EWORD
                                              + e0 + ep * 2];
        sPh[i] = __float22half2_rn(f);
    }
    __syncthreads();

    const int el2 = tid & 31;
    const int wl  = tid >> 5;
    const float2 bias = *(const float2*)&cb[e0 + el2 * 2];

    for (int it = 0; it < 16; it++) {
        const int wloc = it * 16 + wl;
        const int* cid = ps + (w0 + wloc) * MW;

        int off[MW];
#pragma unroll
        for (int j = 0; j < MW; j++)
            off[j] = __ldg(&cid[j]) * (KW * 32) + el2;

        __half2 mh = __float2half2_rn(-60000.f);
#pragma unroll
        for (int t = 0; t < T_OUT; t++) {
            const __half2 u0 = sPh[off[t + 0] + 0 * 32];
            const __half2 u1 = sPh[off[t + 1] + 1 * 32];
            const __half2 u2 = sPh[off[t + 2] + 2 * 32];
            const __half2 u3 = sPh[off[t + 3] + 3 * 32];
            const __half2 u4 = sPh[off[t + 4] + 4 * 32];
            const __half2 s = __hadd2(__hadd2(__hadd2(u0, u1),
                                              __hadd2(u2, u3)), u4);
            mh = __hmax2(mh, s);
        }
        const float2 f = __half22float2(mh);
        sY[(el2 * 2 + 0) * SY_STRIDE + wloc] = fmaxf(f.x + bias.x, 0.f);
        sY[(el2 * 2 + 1) * SY_STRIDE + wloc] = fmaxf(f.y + bias.y, 0.f);
    }
    __syncthreads();

    for (int i = tid; i < 64 * 256; i += 512) {
        const int w = i >> 6, e = i & 63;
        const float y = sY[e * SY_STRIDE + w];
        const int gi = (w0 + w) * EWORD + e0 + e;
        g_Y[gi]  = y;
        g_Yf[gi] = __float2half_rn(y);
    }
}

// ---------------------------------------------------------------------------
// Kernel 3: highway dual-GEMM, single-term fp16, K-chunks of 64, 3-stage
// cp.async pipeline, 2 CTAs/SM, SMEM-staged coalesced epilogue.
// CTA 256 thr (8 warps: 2m x 4n), tile 128m x 128 interleaved rows (64 n).
// grid (256, 4).
// ---------------------------------------------------------------------------
#define RSTR    144                     // 128B data + 16B pad
#define OFF_A   0
#define OFF_B   18432
#define STAGE_B 36864
#define SM3_B   (3 * STAGE_B)           // 110592
#define EPI_STR 68                      // epilogue smem stride (floats)

static __device__ __forceinline__ void stage_chunk(uint32_t sb, int tid,
                                                   int m0, int rb, int kb) {
#pragma unroll
    for (int q = 0; q < 4; q++) {
        const int idx = tid + q * 256;
        const int r = idx >> 3, c = idx & 7;
        const uint32_t so = r * RSTR + c * 16;
        CP16(sb + OFF_A + so,
             (const char*)g_Yf + ((long)(m0 + r) * EWORD + kb + c * 8) * 2);
        CP16(sb + OFF_B + so,
             (const char*)g_Wf + ((long)(rb + r) * EWORD + kb + c * 8) * 2);
    }
    CP_COMMIT();
}

__global__ void __launch_bounds__(256, 2)
highway_mma(const float* __restrict__ bp, const float* __restrict__ bg,
            float* __restrict__ out) {
    extern __shared__ char sm[];
    const uint32_t smb = smem_u32(sm);

    const int tid = threadIdx.x;
    const int wid = tid >> 5;
    const int lane = tid & 31;
    const int wm = wid & 1;          // 64m each
    const int wn = wid >> 1;         // 32 interleaved rows each
    const int m0 = blockIdx.x * 128;
    const int rb = blockIdx.y * 128;

    float acc[4][4][4];
#pragma unroll
    for (int i = 0; i < 4; i++)
#pragma unroll
        for (int j = 0; j < 4; j++)
#pragma unroll
            for (int c = 0; c < 4; c++) acc[i][j][c] = 0.f;

    const int laneRow = lane & 15;
    const int laneHi  = (lane >> 4) * 16;

    stage_chunk(smb + 0 * STAGE_B, tid, m0, rb, 0);
    stage_chunk(smb + 1 * STAGE_B, tid, m0, rb, 64);
    stage_chunk(smb + 2 * STAGE_B, tid, m0, rb, 128);

#pragma unroll
    for (int ch = 0; ch < 4; ch++) {
        if (ch <= 1) CP_WAIT2();
        else if (ch == 2) CP_WAIT1();
        else CP_WAIT0();
        __syncthreads();
        const uint32_t st = smb + (uint32_t)(ch % 3) * STAGE_B;

#pragma unroll
        for (int ks = 0; ks < 4; ks++) {
            const uint32_t kboff = ks * 32 + laneHi;

            uint32_t af[4][4];
#pragma unroll
            for (int mt = 0; mt < 4; mt++)
                LDSM4(af[mt], st + OFF_A
                      + (wm * 64 + mt * 16 + laneRow) * RSTR + kboff);

            uint32_t b0[4], b1[4];
#pragma unroll
            for (int tp = 0; tp < 2; tp++) {
                uint32_t q[4];
                LDSM4(q, st + OFF_B
                      + (wn * 32 + tp * 16 + laneRow) * RSTR + kboff);
                b0[2*tp] = q[0]; b0[2*tp+1] = q[1];
                b1[2*tp] = q[2]; b1[2*tp+1] = q[3];
            }

#pragma unroll
            for (int mt = 0; mt < 4; mt++)
#pragma unroll
                for (int j = 0; j < 4; j++)
                    MMA_F16(acc[mt][j], af[mt], b0[j], b1[j]);
        }

        __syncthreads();
        if (ch + 3 < 4)
            stage_chunk(smb + (uint32_t)(ch % 3) * STAGE_B, tid, m0, rb,
                        (ch + 3) * 64);
    }

    // ---- Epilogue phase 1: (p, g) to conflict-free padded SMEM tiles ----
    float* sPf = (float*)sm;                  // [128][EPI_STR]
    float* sGf = sPf + 128 * EPI_STR;         // [128][EPI_STR]
    const int nb  = rb >> 1;                  // 64-wide n base
    const int nl0 = wn * 16 + (lane & 3);

#pragma unroll
    for (int mt = 0; mt < 4; mt++) {
        const int ml = wm * 64 + mt * 16 + (lane >> 2);
#pragma unroll
        for (int j = 0; j < 4; j++) {
            const int nl = nl0 + j * 4;
            const float bpn = __ldg(&bp[nb + nl]);
            const float bgn = __ldg(&bg[nb + nl]);
            sPf[ml * EPI_STR + nl] = fmaxf(acc[mt][j][0] + bpn, 0.f);
            sGf[ml * EPI_STR + nl] =
                1.f / (1.f + __expf(-(acc[mt][j][1] + bgn)));
            sPf[(ml + 8) * EPI_STR + nl] = fmaxf(acc[mt][j][2] + bpn, 0.f);
            sGf[(ml + 8) * EPI_STR + nl] =
                1.f / (1.f + __expf(-(acc[mt][j][3] + bgn)));
        }
    }
    __syncthreads();

    // ---- Epilogue phase 2: fully coalesced float4 pass ----
#pragma unroll
    for (int q = 0; q < 8; q++) {
        const int i  = tid + q * 256;         // 0..2047
        const int ml = i >> 4;
        const int c4 = (i & 15) << 2;
        const int gi = (m0 + ml) * EWORD + nb + c4;
        const float4 y4 = *(const float4*)&g_Y[gi];
        const float4 p4 = *(const float4*)&sPf[ml * EPI_STR + c4];
        const float4 g4 = *(const float4*)&sGf[ml * EPI_STR + c4];
        float4 o;
        o.x = g4.x * p4.x + (1.f - g4.x) * y4.x;
        o.y = g4.y * p4.y + (1.f - g4.y) * y4.y;
        o.z = g4.z * p4.z + (1.f - g4.z) * y4.z;
        o.w = g4.w * p4.w + (1.f - g4.w) * y4.w;
        *(float4*)&out[gi] = o;
    }
}

// ---------------------------------------------------------------------------
extern "C" void kernel_launch(void* const* d_in, const int* in_sizes, int n_in,
                              void* d_out, int out_size) {
    const int*   ps  = (const int*)d_in[0];
    const float* emb = (const float*)d_in[1];
    const float* cw  = (const float*)d_in[2];
    const float* cb  = (const float*)d_in[3];
    const float* wp  = (const float*)d_in[4];
    const float* bpv = (const float*)d_in[5];
    const float* wg  = (const float*)d_in[6];
    const float* bgv = (const float*)d_in[7];
    float* out = (float*)d_out;

    precomputeP<<<EWORD / 2, 512>>>(emb, cw);

    const int smem2 = VOCAB * KW * 32 * 4 + 64 * SY_STRIDE * 4;
    cudaFuncSetAttribute(conv_max_kernel,
                         cudaFuncAttributeMaxDynamicSharedMemorySize, smem2);
    conv_max_kernel<<<dim3(128, 5), 512, smem2>>>(ps, cb, wp, wg);

    cudaFuncSetAttribute(highway_mma,
                         cudaFuncAttributeMaxDynamicSharedMemorySize, SM3_B);
    highway_mma<<<dim3(NWORDS / 128, 4), 256, SM3_B>>>(bpv, bgv, out);
}